// round 1
// baseline (speedup 1.0000x reference)
#include <cuda_runtime.h>
#include <cuda_bf16.h>
#include <cstdint>

#define SEQ    256
#define BATCH  32
#define REC    16
#define EMB    32
#define VOCAB  32000
#define NROWS  (SEQ * BATCH)   // 8192

// ---- scratch (no allocations allowed) ----
__device__ float          g_Apre[NROWS * REC];     // x_t @ U^T + b1 + b2
__device__ __nv_bfloat16  g_hidden[NROWS * REC];   // hidden states (pre-step), bf16
__device__ __nv_bfloat16  g_Vb[VOCAB * REC];       // V in bf16
__device__ float          g_rowc[NROWS];           // ln(sum exp(logit)) per row

__device__ __forceinline__ float ex2f(float x) { float y; asm("ex2.approx.f32 %0, %1;" : "=f"(y) : "f"(x)); return y; }
__device__ __forceinline__ float lg2f(float x) { float y; asm("lg2.approx.f32 %0, %1;" : "=f"(y) : "f"(x)); return y; }
__device__ __forceinline__ float rcpf(float x) { float y; asm("rcp.approx.f32 %0, %1;" : "=f"(y) : "f"(x)); return y; }

#define L2E 1.4426950408889634f
#define LN2 0.6931471805599453f

__device__ __forceinline__ void mma16816(float d[4], const uint32_t a[4], uint32_t b0, uint32_t b1) {
    asm("mma.sync.aligned.m16n8k16.row.col.f32.bf16.bf16.f32 "
        "{%0,%1,%2,%3}, {%4,%5,%6,%7}, {%8,%9}, {%10,%11,%12,%13};"
        : "=f"(d[0]), "=f"(d[1]), "=f"(d[2]), "=f"(d[3])
        : "r"(a[0]), "r"(a[1]), "r"(a[2]), "r"(a[3]),
          "r"(b0), "r"(b1),
          "f"(0.0f), "f"(0.0f), "f"(0.0f), "f"(0.0f));
}

// ---------------- Kernel 1: A_pre = emb[token] @ U^T + b1 + b2 ----------------
__global__ void k_embed(const int* __restrict__ tok, const float* __restrict__ emb,
                        const float* __restrict__ U, const float* __restrict__ b1,
                        const float* __restrict__ b2) {
    int tid = blockIdx.x * blockDim.x + threadIdx.x;
    if (tid >= NROWS * REC) return;
    int rid = tid >> 4;
    int r   = tid & 15;
    int tk  = tok[rid];
    const float* e = emb + (size_t)tk * EMB;
    const float* u = U + r * EMB;
    float acc = b1[r] + b2[r];
    #pragma unroll
    for (int i = 0; i < EMB; i++) acc = fmaf(e[i], u[i], acc);
    g_Apre[tid] = acc;   // tid == rid*16 + r
}

// ---------------- Kernel 2: V fp32 -> bf16 ----------------
__global__ void k_vconv(const float* __restrict__ V) {
    int i = blockIdx.x * blockDim.x + threadIdx.x;
    if (i < VOCAB * REC) g_Vb[i] = __float2bfloat16(V[i]);
}

// ---------------- Kernel 3: serial recurrence (1 warp per 2 batches) ----------------
// hidden[s] = state BEFORE step s (reference scan collects pre-state).
__global__ void k_rnn(const float* __restrict__ W, const float* __restrict__ h0v) {
    int lane = threadIdx.x;                 // 32 threads
    int b = blockIdx.x * 2 + (lane >> 4);   // 16 blocks -> 32 batches
    int r = lane & 15;
    float w[REC];
    #pragma unroll
    for (int j = 0; j < REC; j++) w[j] = W[r * REC + j];
    float h = h0v[r];
    g_hidden[b * REC + r] = __float2bfloat16(h);   // s = 0
    float anext = g_Apre[b * REC + r];             // t = 0
    for (int t = 0; t < SEQ - 1; t++) {
        float a = anext;
        if (t < SEQ - 2) anext = g_Apre[((t + 1) * BATCH + b) * REC + r];
        float s0 = a, s1 = 0.0f;
        #pragma unroll
        for (int j = 0; j < REC; j += 2) {
            float hj = __shfl_sync(0xffffffffu, h, j,     16);
            float hk = __shfl_sync(0xffffffffu, h, j + 1, 16);
            s0 = fmaf(hj, w[j],     s0);
            s1 = fmaf(hk, w[j + 1], s1);
        }
        float z  = (s0 + s1) * (2.0f * L2E);             // 2x * log2(e)
        float ez = ex2f(z);                              // e^{2x}
        h = 1.0f - 2.0f * rcpf(ez + 1.0f);               // tanh(x)
        g_hidden[((t + 1) * BATCH + b) * REC + r] = __float2bfloat16(h);
    }
}

// ---- A-fragment loader shared by pass 1/2.
// Row layout: 16 bf16 per row = 8 uint32; pair (2t,2t+1) = u32 idx t; (2t+8,2t+9) = t+4.
__device__ __forceinline__ void load_afrag(uint32_t a[2][4], int tile, int g, int t) {
    const uint32_t* H = (const uint32_t*)g_hidden;
    #pragma unroll
    for (int f = 0; f < 2; f++) {
        int r0 = tile + f * 16 + g;
        int r1 = r0 + 8;
        a[f][0] = H[r0 * 8 + t];
        a[f][1] = H[r1 * 8 + t];
        a[f][2] = H[r0 * 8 + t + 4];
        a[f][3] = H[r1 * 8 + t + 4];
    }
}

// ---------------- Kernel 4 (pass 1): per-row ln(sum exp(logit)) ----------------
// Grid: 256 blocks (32 rows each), 8 warps; warp owns a 4000-wide vocab slice.
__global__ void k_sum() {
    const int lane = threadIdx.x & 31, warp = threadIdx.x >> 5;
    const int g = lane >> 2, t = lane & 3;
    const int tile = blockIdx.x * 32;

    uint32_t a[2][4];
    load_afrag(a, tile, g, t);

    const uint32_t* Vb32 = (const uint32_t*)g_Vb;
    float s00 = 0.f, s01 = 0.f, s10 = 0.f, s11 = 0.f;
    const int vend = (warp + 1) * 4000;
    #pragma unroll 4
    for (int v = warp * 4000; v < vend; v += 8) {
        int col = v + g;
        uint32_t b0 = Vb32[col * 8 + t];
        uint32_t b1 = Vb32[col * 8 + t + 4];
        float d[4];
        mma16816(d, a[0], b0, b1);
        s00 += ex2f(d[0] * L2E) + ex2f(d[1] * L2E);
        s01 += ex2f(d[2] * L2E) + ex2f(d[3] * L2E);
        mma16816(d, a[1], b0, b1);
        s10 += ex2f(d[0] * L2E) + ex2f(d[1] * L2E);
        s11 += ex2f(d[2] * L2E) + ex2f(d[3] * L2E);
    }
    // reduce across the 4 t-lanes (bits 0..1)
    #pragma unroll
    for (int m = 1; m <= 2; m <<= 1) {
        s00 += __shfl_xor_sync(0xffffffffu, s00, m);
        s01 += __shfl_xor_sync(0xffffffffu, s01, m);
        s10 += __shfl_xor_sync(0xffffffffu, s10, m);
        s11 += __shfl_xor_sync(0xffffffffu, s11, m);
    }
    __shared__ float red[8][32];
    if (t == 0) {
        red[warp][g]      = s00;
        red[warp][g + 8]  = s01;
        red[warp][g + 16] = s10;
        red[warp][g + 24] = s11;
    }
    __syncthreads();
    if (threadIdx.x < 32) {
        float tot = 0.f;
        #pragma unroll
        for (int wq = 0; wq < 8; wq++) tot += red[wq][threadIdx.x];
        g_rowc[tile + threadIdx.x] = LN2 * lg2f(tot);   // ln(sum)
    }
}

// ---------------- Kernel 5 (pass 2): out = logit - ln(sum) ----------------
__global__ void k_out(float* __restrict__ out) {
    const int lane = threadIdx.x & 31, warp = threadIdx.x >> 5;
    const int g = lane >> 2, t = lane & 3;
    const int tile = blockIdx.x * 32;

    uint32_t a[2][4];
    load_afrag(a, tile, g, t);

    const float c00 = g_rowc[tile + g];
    const float c01 = g_rowc[tile + g + 8];
    const float c10 = g_rowc[tile + g + 16];
    const float c11 = g_rowc[tile + g + 24];

    const uint32_t* Vb32 = (const uint32_t*)g_Vb;
    float* base0 = out + (size_t)(tile + g) * VOCAB + 2 * t;        // row g
    const int vend = (warp + 1) * 4000;
    #pragma unroll 4
    for (int v = warp * 4000; v < vend; v += 8) {
        int col = v + g;
        uint32_t b0 = Vb32[col * 8 + t];
        uint32_t b1 = Vb32[col * 8 + t + 4];
        float d[4];
        mma16816(d, a[0], b0, b1);
        *(float2*)(base0 + v)                        = make_float2(d[0] - c00, d[1] - c00);
        *(float2*)(base0 + v + (size_t)8  * VOCAB)   = make_float2(d[2] - c01, d[3] - c01);
        mma16816(d, a[1], b0, b1);
        *(float2*)(base0 + v + (size_t)16 * VOCAB)   = make_float2(d[0] - c10, d[1] - c10);
        *(float2*)(base0 + v + (size_t)24 * VOCAB)   = make_float2(d[2] - c11, d[3] - c11);
    }
}

extern "C" void kernel_launch(void* const* d_in, const int* in_sizes, int n_in,
                              void* d_out, int out_size) {
    const int*   tok = (const int*)d_in[0];
    const float* emb = (const float*)d_in[1];
    const float* U   = (const float*)d_in[2];
    const float* W   = (const float*)d_in[3];
    const float* V   = (const float*)d_in[4];
    const float* b1  = (const float*)d_in[5];
    const float* b2  = (const float*)d_in[6];
    const float* h0  = (const float*)d_in[7];
    float* out = (float*)d_out;

    k_embed<<<(NROWS * REC + 255) / 256, 256>>>(tok, emb, U, b1, b2);
    k_vconv<<<(VOCAB * REC + 255) / 256, 256>>>(V);
    k_rnn<<<BATCH / 2, 32>>>(W, h0);
    k_sum<<<NROWS / 32, 256>>>();
    k_out<<<NROWS / 32, 256>>>(out);
}

// round 2
// speedup vs baseline: 1.1510x; 1.1510x over previous
#include <cuda_runtime.h>
#include <cuda_bf16.h>
#include <cuda_fp16.h>
#include <cstdint>

#define SEQ    256
#define BATCH  32
#define REC    16
#define EMB    32
#define VOCAB  32000
#define NROWS  (SEQ * BATCH)   // 8192
#define VS     4               // vocab splits (grid expansion)

// ---- scratch (no allocations allowed) ----
__device__ float          g_Apre[NROWS * REC];      // x_t @ U^T + b1 + b2
__device__ __nv_bfloat16  g_hidden[NROWS * REC];    // hidden states (pre-step), bf16
__device__ __nv_bfloat16  g_hiddenL[NROWS * REC];   // hidden * log2(e), bf16 (pass-1 A)
__device__ __nv_bfloat16  g_Vb[VOCAB * REC];        // V in bf16
__device__ float          g_part[VS][NROWS];        // partial sum-exp per vocab split

__device__ __forceinline__ float ex2f(float x) { float y; asm("ex2.approx.f32 %0, %1;" : "=f"(y) : "f"(x)); return y; }
__device__ __forceinline__ float lg2f(float x) { float y; asm("lg2.approx.f32 %0, %1;" : "=f"(y) : "f"(x)); return y; }
__device__ __forceinline__ float rcpf(float x) { float y; asm("rcp.approx.f32 %0, %1;" : "=f"(y) : "f"(x)); return y; }

#define L2E 1.4426950408889634f
#define LN2 0.6931471805599453f

__device__ __forceinline__ void mma16816(float d[4], const uint32_t a[4], uint32_t b0, uint32_t b1) {
    asm("mma.sync.aligned.m16n8k16.row.col.f32.bf16.bf16.f32 "
        "{%0,%1,%2,%3}, {%4,%5,%6,%7}, {%8,%9}, {%10,%11,%12,%13};"
        : "=f"(d[0]), "=f"(d[1]), "=f"(d[2]), "=f"(d[3])
        : "r"(a[0]), "r"(a[1]), "r"(a[2]), "r"(a[3]),
          "r"(b0), "r"(b1),
          "f"(0.0f), "f"(0.0f), "f"(0.0f), "f"(0.0f));
}

// 2^x + 2^y via one ex2.approx.f16x2 (inputs already log2-domain, |x|<6 so f16-safe)
__device__ __forceinline__ float exp2sum2(float x, float y) {
    __half2 h = __floats2half2_rn(x, y);
    uint32_t u = *reinterpret_cast<uint32_t*>(&h);
    uint32_t r;
    asm("ex2.approx.f16x2 %0, %1;" : "=r"(r) : "r"(u));
    __half2 e = *reinterpret_cast<__half2*>(&r);
    float2 f = __half22float2(e);
    return f.x + f.y;
}

// ---------------- Kernel 1 (fused prep): V->bf16  +  A_pre = emb[tok]@U^T + b1 + b2 ----
__global__ void k_prep(const int* __restrict__ tok, const float* __restrict__ emb,
                       const float* __restrict__ U, const float* __restrict__ V,
                       const float* __restrict__ b1, const float* __restrict__ b2) {
    int i = blockIdx.x * blockDim.x + threadIdx.x;
    if (i < VOCAB * REC) g_Vb[i] = __float2bfloat16(V[i]);
    if (i < NROWS * REC) {
        int rid = i >> 4;
        int r   = i & 15;
        int tk  = tok[rid];
        const float* e = emb + (size_t)tk * EMB;
        const float* u = U + r * EMB;
        float acc = b1[r] + b2[r];
        #pragma unroll
        for (int k = 0; k < EMB; k++) acc = fmaf(e[k], u[k], acc);
        g_Apre[i] = acc;
    }
}

// ---------------- Kernel 2: serial recurrence (1 warp per 2 batches) ----------------
__global__ void k_rnn(const float* __restrict__ W, const float* __restrict__ h0v) {
    int lane = threadIdx.x;                 // 32 threads
    int b = blockIdx.x * 2 + (lane >> 4);   // 16 blocks -> 32 batches
    int r = lane & 15;
    float w[REC];
    #pragma unroll
    for (int j = 0; j < REC; j++) w[j] = W[r * REC + j];
    float h = h0v[r];
    g_hidden[b * REC + r]  = __float2bfloat16(h);           // s = 0
    g_hiddenL[b * REC + r] = __float2bfloat16(h * L2E);
    float anext = g_Apre[b * REC + r];                      // t = 0
    for (int t = 0; t < SEQ - 1; t++) {
        float a = anext;
        if (t < SEQ - 2) anext = g_Apre[((t + 1) * BATCH + b) * REC + r];
        float s0 = a, s1 = 0.0f;
        #pragma unroll
        for (int j = 0; j < REC; j += 2) {
            float hj = __shfl_sync(0xffffffffu, h, j,     16);
            float hk = __shfl_sync(0xffffffffu, h, j + 1, 16);
            s0 = fmaf(hj, w[j],     s0);
            s1 = fmaf(hk, w[j + 1], s1);
        }
        float z  = (s0 + s1) * (2.0f * L2E);
        float ez = ex2f(z);
        h = 1.0f - 2.0f * rcpf(ez + 1.0f);                  // tanh
        int idx = ((t + 1) * BATCH + b) * REC + r;
        g_hidden[idx]  = __float2bfloat16(h);
        g_hiddenL[idx] = __float2bfloat16(h * L2E);
    }
}

// ---- A-fragment loader (16 bf16/row = 8 u32; pair (2t,2t+1)=u32 t; (2t+8,2t+9)=t+4)
__device__ __forceinline__ void load_afrag(uint32_t a[2][4], const __nv_bfloat16* src,
                                           int tile, int g, int t) {
    const uint32_t* H = (const uint32_t*)src;
    #pragma unroll
    for (int f = 0; f < 2; f++) {
        int r0 = tile + f * 16 + g;
        int r1 = r0 + 8;
        a[f][0] = H[r0 * 8 + t];
        a[f][1] = H[r1 * 8 + t];
        a[f][2] = H[r0 * 8 + t + 4];
        a[f][3] = H[r1 * 8 + t + 4];
    }
}

// ---------------- Kernel 3 (pass 1): partial sum exp(logit) per row ----------------
// Grid: (256 row-tiles, VS vocab-splits), 8 warps; warp covers 1000 vocab cols.
__global__ void k_sum() {
    const int lane = threadIdx.x & 31, warp = threadIdx.x >> 5;
    const int g = lane >> 2, t = lane & 3;
    const int tile  = blockIdx.x * 32;
    const int split = blockIdx.y;

    uint32_t a[2][4];
    load_afrag(a, g_hiddenL, tile, g, t);   // log2-domain A

    const uint32_t* Vb32 = (const uint32_t*)g_Vb;
    float s00 = 0.f, s01 = 0.f, s10 = 0.f, s11 = 0.f;
    const int v0 = split * (VOCAB / VS) + warp * (VOCAB / VS / 8);
    const int vend = v0 + (VOCAB / VS / 8);
    #pragma unroll 5
    for (int v = v0; v < vend; v += 8) {
        int col = v + g;
        uint32_t b0 = Vb32[col * 8 + t];
        uint32_t b1 = Vb32[col * 8 + t + 4];
        float d[4];
        mma16816(d, a[0], b0, b1);
        s00 += exp2sum2(d[0], d[1]);
        s01 += exp2sum2(d[2], d[3]);
        mma16816(d, a[1], b0, b1);
        s10 += exp2sum2(d[0], d[1]);
        s11 += exp2sum2(d[2], d[3]);
    }
    // reduce across the 4 t-lanes
    #pragma unroll
    for (int m = 1; m <= 2; m <<= 1) {
        s00 += __shfl_xor_sync(0xffffffffu, s00, m);
        s01 += __shfl_xor_sync(0xffffffffu, s01, m);
        s10 += __shfl_xor_sync(0xffffffffu, s10, m);
        s11 += __shfl_xor_sync(0xffffffffu, s11, m);
    }
    __shared__ float red[8][32];
    if (t == 0) {
        red[warp][g]      = s00;
        red[warp][g + 8]  = s01;
        red[warp][g + 16] = s10;
        red[warp][g + 24] = s11;
    }
    __syncthreads();
    if (threadIdx.x < 32) {
        float tot = 0.f;
        #pragma unroll
        for (int wq = 0; wq < 8; wq++) tot += red[wq][threadIdx.x];
        g_part[split][tile + threadIdx.x] = tot;
    }
}

__device__ __forceinline__ float row_const(int row) {
    float s = g_part[0][row] + g_part[1][row] + g_part[2][row] + g_part[3][row];
    return LN2 * lg2f(s);
}

// ---------------- Kernel 4 (pass 2): out = logit - ln(sum) ----------------
__global__ void k_out(float* __restrict__ out) {
    const int lane = threadIdx.x & 31, warp = threadIdx.x >> 5;
    const int g = lane >> 2, t = lane & 3;
    const int tile  = blockIdx.x * 32;
    const int split = blockIdx.y;

    uint32_t a[2][4];
    load_afrag(a, g_hidden, tile, g, t);

    const float c00 = row_const(tile + g);
    const float c01 = row_const(tile + g + 8);
    const float c10 = row_const(tile + g + 16);
    const float c11 = row_const(tile + g + 24);

    const uint32_t* Vb32 = (const uint32_t*)g_Vb;
    float* base0 = out + (size_t)(tile + g) * VOCAB + 2 * t;
    const int v0 = split * (VOCAB / VS) + warp * (VOCAB / VS / 8);
    const int vend = v0 + (VOCAB / VS / 8);
    #pragma unroll 5
    for (int v = v0; v < vend; v += 8) {
        int col = v + g;
        uint32_t b0 = Vb32[col * 8 + t];
        uint32_t b1 = Vb32[col * 8 + t + 4];
        float d[4];
        mma16816(d, a[0], b0, b1);
        *(float2*)(base0 + v)                      = make_float2(d[0] - c00, d[1] - c00);
        *(float2*)(base0 + v + (size_t)8  * VOCAB) = make_float2(d[2] - c01, d[3] - c01);
        mma16816(d, a[1], b0, b1);
        *(float2*)(base0 + v + (size_t)16 * VOCAB) = make_float2(d[0] - c10, d[1] - c10);
        *(float2*)(base0 + v + (size_t)24 * VOCAB) = make_float2(d[2] - c11, d[3] - c11);
    }
}

extern "C" void kernel_launch(void* const* d_in, const int* in_sizes, int n_in,
                              void* d_out, int out_size) {
    const int*   tok = (const int*)d_in[0];
    const float* emb = (const float*)d_in[1];
    const float* U   = (const float*)d_in[2];
    const float* W   = (const float*)d_in[3];
    const float* V   = (const float*)d_in[4];
    const float* b1  = (const float*)d_in[5];
    const float* b2  = (const float*)d_in[6];
    const float* h0  = (const float*)d_in[7];
    float* out = (float*)d_out;

    k_prep<<<(VOCAB * REC + 255) / 256, 256>>>(tok, emb, U, V, b1, b2);
    k_rnn<<<BATCH / 2, 32>>>(W, h0);
    dim3 grid2(NROWS / 32, VS);
    k_sum<<<grid2, 256>>>();
    k_out<<<grid2, 256>>>(out);
}